// round 1
// baseline (speedup 1.0000x reference)
#include <cuda_runtime.h>
#include <math.h>

#define NB 16
#define NTT 1024
#define NSS 1024
#define ND 768

// scratch (static device globals — no allocations allowed)
__device__ float g_scores[NB * NTT * NSS];   // scores -> av (in place)
__device__ float g_c[NB * NTT * ND];         // attention context c
__device__ float g_gate[NB * NSS];           // sigmoid(colsum)

#define ST_TILE(dst, q, r, v) do { (dst)[(q)+0][(r)] = (v).x; (dst)[(q)+1][(r)] = (v).y; \
                                   (dst)[(q)+2][(r)] = (v).z; (dst)[(q)+3][(r)] = (v).w; } while (0)

// ---------------------------------------------------------------------------
// GEMM1 (NT): scores[b] = inputs[b] (1024x768) * context[b]^T (1024x768)^T
// ---------------------------------------------------------------------------
__global__ __launch_bounds__(256, 2)
void gemm1_nt(const float* __restrict__ inp, const float* __restrict__ ctx)
{
    const int b  = blockIdx.z;
    const int m0 = blockIdx.y * 128;
    const int n0 = blockIdx.x * 128;
    const float* A  = inp + (size_t)b * NTT * ND;
    const float* Bm = ctx + (size_t)b * NSS * ND;
    float*       C  = g_scores + (size_t)b * NTT * NSS;
    const int lda = ND, ldb = ND, ldc = NSS, KT = ND / 16;

    __shared__ float As[2][16][132];
    __shared__ float Bs[2][16][132];

    const int tid = threadIdx.x;
    const int tx = tid & 15;
    const int ty = tid >> 4;
    const int r0 = tid >> 2;          // 0..63
    const int r1 = r0 + 64;           // 64..127
    const int kq = (tid & 3) * 4;

    float4 pa0, pa1, pb0, pb1;
    pa0 = *(const float4*)(A  + (size_t)(m0 + r0) * lda + kq);
    pa1 = *(const float4*)(A  + (size_t)(m0 + r1) * lda + kq);
    pb0 = *(const float4*)(Bm + (size_t)(n0 + r0) * ldb + kq);
    pb1 = *(const float4*)(Bm + (size_t)(n0 + r1) * ldb + kq);
    ST_TILE(As[0], kq, r0, pa0); ST_TILE(As[0], kq, r1, pa1);
    ST_TILE(Bs[0], kq, r0, pb0); ST_TILE(Bs[0], kq, r1, pb1);
    __syncthreads();

    float acc[8][8] = {};
    int buf = 0;
    for (int kt = 0; kt < KT; ++kt) {
        const int k0n = (kt + 1) * 16;
        if (kt + 1 < KT) {
            pa0 = *(const float4*)(A  + (size_t)(m0 + r0) * lda + k0n + kq);
            pa1 = *(const float4*)(A  + (size_t)(m0 + r1) * lda + k0n + kq);
            pb0 = *(const float4*)(Bm + (size_t)(n0 + r0) * ldb + k0n + kq);
            pb1 = *(const float4*)(Bm + (size_t)(n0 + r1) * ldb + k0n + kq);
        }
        #pragma unroll
        for (int kk = 0; kk < 16; ++kk) {
            float a[8], bb[8];
            *(float4*)&a[0]  = *(const float4*)&As[buf][kk][ty * 8];
            *(float4*)&a[4]  = *(const float4*)&As[buf][kk][ty * 8 + 4];
            *(float4*)&bb[0] = *(const float4*)&Bs[buf][kk][tx * 8];
            *(float4*)&bb[4] = *(const float4*)&Bs[buf][kk][tx * 8 + 4];
            #pragma unroll
            for (int i = 0; i < 8; ++i)
                #pragma unroll
                for (int j = 0; j < 8; ++j)
                    acc[i][j] = fmaf(a[i], bb[j], acc[i][j]);
        }
        if (kt + 1 < KT) {
            const int nb = buf ^ 1;
            ST_TILE(As[nb], kq, r0, pa0); ST_TILE(As[nb], kq, r1, pa1);
            ST_TILE(Bs[nb], kq, r0, pb0); ST_TILE(Bs[nb], kq, r1, pb1);
        }
        __syncthreads();
        buf ^= 1;
    }
    #pragma unroll
    for (int i = 0; i < 8; ++i) {
        float* crow = C + (size_t)(m0 + ty * 8 + i) * ldc + n0 + tx * 8;
        *(float4*)(crow)     = make_float4(acc[i][0], acc[i][1], acc[i][2], acc[i][3]);
        *(float4*)(crow + 4) = make_float4(acc[i][4], acc[i][5], acc[i][6], acc[i][7]);
    }
}

// ---------------------------------------------------------------------------
// row softmax over S (in place on g_scores)
// ---------------------------------------------------------------------------
__global__ __launch_bounds__(256)
void softmax_k()
{
    float* row = g_scores + (size_t)blockIdx.x * NSS;
    const int tid = threadIdx.x;
    const unsigned FULL = 0xffffffffu;
    float4 x = *(float4*)(row + tid * 4);
    float m = fmaxf(fmaxf(x.x, x.y), fmaxf(x.z, x.w));
    __shared__ float sred[8];
    __shared__ float sred2[8];
    #pragma unroll
    for (int o = 16; o; o >>= 1) m = fmaxf(m, __shfl_xor_sync(FULL, m, o));
    if ((tid & 31) == 0) sred[tid >> 5] = m;
    __syncthreads();
    m = fmaxf(fmaxf(fmaxf(sred[0], sred[1]), fmaxf(sred[2], sred[3])),
              fmaxf(fmaxf(sred[4], sred[5]), fmaxf(sred[6], sred[7])));
    float e0 = expf(x.x - m), e1 = expf(x.y - m), e2 = expf(x.z - m), e3 = expf(x.w - m);
    float s = (e0 + e1) + (e2 + e3);
    #pragma unroll
    for (int o = 16; o; o >>= 1) s += __shfl_xor_sync(FULL, s, o);
    if ((tid & 31) == 0) sred2[tid >> 5] = s;
    __syncthreads();
    s = ((sred2[0] + sred2[1]) + (sred2[2] + sred2[3])) +
        ((sred2[4] + sred2[5]) + (sred2[6] + sred2[7]));
    const float inv = 1.0f / s;
    *(float4*)(row + tid * 4) = make_float4(e0 * inv, e1 * inv, e2 * inv, e3 * inv);
}

// ---------------------------------------------------------------------------
// gate[b,s] = sigmoid( sum_t av[b,t,s] )
// ---------------------------------------------------------------------------
__global__ __launch_bounds__(256)
void gate_k()
{
    const int gid = blockIdx.x * 256 + threadIdx.x;      // 0..16383
    const int b = gid >> 10, s = gid & 1023;
    const float* p = g_scores + (size_t)b * NTT * NSS + s;
    float a[8] = {};
    for (int t = 0; t < NTT; t += 8) {
        #pragma unroll
        for (int u = 0; u < 8; ++u) a[u] += p[(size_t)(t + u) * NSS];
    }
    const float sum = ((a[0] + a[1]) + (a[2] + a[3])) + ((a[4] + a[5]) + (a[6] + a[7]));
    g_gate[gid] = 1.0f / (1.0f + expf(-sum));
}

// ---------------------------------------------------------------------------
// av_g = av * gate * (1/1024), written transposed into d_out region 2: [T,B,S]
// ---------------------------------------------------------------------------
__global__ __launch_bounds__(256)
void avg_k(float* __restrict__ out2)
{
    const int bt = blockIdx.x;                 // b*T + t
    const int b = bt >> 10, t = bt & 1023;
    const int s = threadIdx.x * 4;
    float4 v = *(const float4*)(g_scores + (size_t)bt * NSS + s);
    float4 g = *(const float4*)(g_gate + b * NSS + s);
    const float pool = 1.0f / 1024.0f;
    v.x *= g.x * pool; v.y *= g.y * pool; v.z *= g.z * pool; v.w *= g.w * pool;
    *(float4*)(out2 + ((size_t)t * NB + b) * NSS + s) = v;
}

// ---------------------------------------------------------------------------
// GEMM2 (NN): c[b] (1024x768) = av_g[b] (1024x1024, read from out2 with
//             row stride NB*NSS) * context[b] (1024x768)
// ---------------------------------------------------------------------------
__global__ __launch_bounds__(256, 2)
void gemm2_nn(const float* __restrict__ out2, const float* __restrict__ ctx)
{
    const int b  = blockIdx.z;
    const int m0 = blockIdx.y * 128;
    const int n0 = blockIdx.x * 128;
    const float* A  = out2 + (size_t)b * NSS;          // row t at t*(NB*NSS)
    const float* Bm = ctx + (size_t)b * NSS * ND;      // [K=1024, N=768] row-major
    float*       C  = g_c + (size_t)b * NTT * ND;
    const int lda = NB * NSS, ldb = ND, ldc = ND, KT = NSS / 16;

    __shared__ float As[2][16][132];
    __shared__ float Bs[2][16][132];

    const int tid = threadIdx.x;
    const int tx = tid & 15;
    const int ty = tid >> 4;
    // A loader (transpose to As[k][m])
    const int r0 = tid >> 2, r1 = r0 + 64;
    const int kq = (tid & 3) * 4;
    // B loader (direct Bs[k][n])
    const int kk0 = tid >> 5, kk1 = kk0 + 8;           // 0..7 / 8..15
    const int nq  = (tid & 31) * 4;

    float4 pa0, pa1, pb0, pb1;
    pa0 = *(const float4*)(A  + (size_t)(m0 + r0) * lda + kq);
    pa1 = *(const float4*)(A  + (size_t)(m0 + r1) * lda + kq);
    pb0 = *(const float4*)(Bm + (size_t)kk0 * ldb + n0 + nq);
    pb1 = *(const float4*)(Bm + (size_t)kk1 * ldb + n0 + nq);
    ST_TILE(As[0], kq, r0, pa0); ST_TILE(As[0], kq, r1, pa1);
    *(float4*)&Bs[0][kk0][nq] = pb0;
    *(float4*)&Bs[0][kk1][nq] = pb1;
    __syncthreads();

    float acc[8][8] = {};
    int buf = 0;
    for (int kt = 0; kt < KT; ++kt) {
        const int k0n = (kt + 1) * 16;
        if (kt + 1 < KT) {
            pa0 = *(const float4*)(A  + (size_t)(m0 + r0) * lda + k0n + kq);
            pa1 = *(const float4*)(A  + (size_t)(m0 + r1) * lda + k0n + kq);
            pb0 = *(const float4*)(Bm + (size_t)(k0n + kk0) * ldb + n0 + nq);
            pb1 = *(const float4*)(Bm + (size_t)(k0n + kk1) * ldb + n0 + nq);
        }
        #pragma unroll
        for (int kk = 0; kk < 16; ++kk) {
            float a[8], bb[8];
            *(float4*)&a[0]  = *(const float4*)&As[buf][kk][ty * 8];
            *(float4*)&a[4]  = *(const float4*)&As[buf][kk][ty * 8 + 4];
            *(float4*)&bb[0] = *(const float4*)&Bs[buf][kk][tx * 8];
            *(float4*)&bb[4] = *(const float4*)&Bs[buf][kk][tx * 8 + 4];
            #pragma unroll
            for (int i = 0; i < 8; ++i)
                #pragma unroll
                for (int j = 0; j < 8; ++j)
                    acc[i][j] = fmaf(a[i], bb[j], acc[i][j]);
        }
        if (kt + 1 < KT) {
            const int nb = buf ^ 1;
            ST_TILE(As[nb], kq, r0, pa0); ST_TILE(As[nb], kq, r1, pa1);
            *(float4*)&Bs[nb][kk0][nq] = pb0;
            *(float4*)&Bs[nb][kk1][nq] = pb1;
        }
        __syncthreads();
        buf ^= 1;
    }
    #pragma unroll
    for (int i = 0; i < 8; ++i) {
        float* crow = C + (size_t)(m0 + ty * 8 + i) * ldc + n0 + tx * 8;
        *(float4*)(crow)     = make_float4(acc[i][0], acc[i][1], acc[i][2], acc[i][3]);
        *(float4*)(crow + 4) = make_float4(acc[i][4], acc[i][5], acc[i][6], acc[i][7]);
    }
}

// ---------------------------------------------------------------------------
// GEMM3 (NT, fused): h[m,n] = sum_k X[m,k] * W[n,k] + b_out[n]; PReLU;
//   X[:, 0:768)   = g_c * w_scale + b_scale
//   X[:, 768:1536)= inputs
// written transposed to out1 (m = b*T+t -> out1[t, b, n])
// ---------------------------------------------------------------------------
__global__ __launch_bounds__(256, 2)
void gemm3_fused(const float* __restrict__ inp, const float* __restrict__ W,
                 const float* __restrict__ b_out, const float* __restrict__ wsp,
                 const float* __restrict__ bsp, const float* __restrict__ pap,
                 float* __restrict__ out1)
{
    const int m0 = blockIdx.y * 128;   // over B*T = 16384
    const int n0 = blockIdx.x * 128;   // over 768
    const int ldb = 2 * ND, KT = (2 * ND) / 16;   // K = 1536

    const float ws = __ldg(wsp);
    const float bs = __ldg(bsp);

    __shared__ float As[2][16][132];
    __shared__ float Bs[2][16][132];

    const int tid = threadIdx.x;
    const int tx = tid & 15;
    const int ty = tid >> 4;
    const int r0 = tid >> 2, r1 = r0 + 64;
    const int kq = (tid & 3) * 4;

    float4 pa0, pa1, pb0, pb1;
    // tile 0: k0 = 0 < 768 -> c with affine
    pa0 = *(const float4*)(g_c + (size_t)(m0 + r0) * ND + kq);
    pa1 = *(const float4*)(g_c + (size_t)(m0 + r1) * ND + kq);
    pa0.x = fmaf(pa0.x, ws, bs); pa0.y = fmaf(pa0.y, ws, bs);
    pa0.z = fmaf(pa0.z, ws, bs); pa0.w = fmaf(pa0.w, ws, bs);
    pa1.x = fmaf(pa1.x, ws, bs); pa1.y = fmaf(pa1.y, ws, bs);
    pa1.z = fmaf(pa1.z, ws, bs); pa1.w = fmaf(pa1.w, ws, bs);
    pb0 = *(const float4*)(W + (size_t)(n0 + r0) * ldb + kq);
    pb1 = *(const float4*)(W + (size_t)(n0 + r1) * ldb + kq);
    ST_TILE(As[0], kq, r0, pa0); ST_TILE(As[0], kq, r1, pa1);
    ST_TILE(Bs[0], kq, r0, pb0); ST_TILE(Bs[0], kq, r1, pb1);
    __syncthreads();

    float acc[8][8] = {};
    int buf = 0;
    for (int kt = 0; kt < KT; ++kt) {
        const int k0n = (kt + 1) * 16;
        if (kt + 1 < KT) {
            if (k0n < ND) {
                pa0 = *(const float4*)(g_c + (size_t)(m0 + r0) * ND + k0n + kq);
                pa1 = *(const float4*)(g_c + (size_t)(m0 + r1) * ND + k0n + kq);
                pa0.x = fmaf(pa0.x, ws, bs); pa0.y = fmaf(pa0.y, ws, bs);
                pa0.z = fmaf(pa0.z, ws, bs); pa0.w = fmaf(pa0.w, ws, bs);
                pa1.x = fmaf(pa1.x, ws, bs); pa1.y = fmaf(pa1.y, ws, bs);
                pa1.z = fmaf(pa1.z, ws, bs); pa1.w = fmaf(pa1.w, ws, bs);
            } else {
                pa0 = *(const float4*)(inp + (size_t)(m0 + r0) * ND + (k0n - ND) + kq);
                pa1 = *(const float4*)(inp + (size_t)(m0 + r1) * ND + (k0n - ND) + kq);
            }
            pb0 = *(const float4*)(W + (size_t)(n0 + r0) * ldb + k0n + kq);
            pb1 = *(const float4*)(W + (size_t)(n0 + r1) * ldb + k0n + kq);
        }
        #pragma unroll
        for (int kk = 0; kk < 16; ++kk) {
            float a[8], bb[8];
            *(float4*)&a[0]  = *(const float4*)&As[buf][kk][ty * 8];
            *(float4*)&a[4]  = *(const float4*)&As[buf][kk][ty * 8 + 4];
            *(float4*)&bb[0] = *(const float4*)&Bs[buf][kk][tx * 8];
            *(float4*)&bb[4] = *(const float4*)&Bs[buf][kk][tx * 8 + 4];
            #pragma unroll
            for (int i = 0; i < 8; ++i)
                #pragma unroll
                for (int j = 0; j < 8; ++j)
                    acc[i][j] = fmaf(a[i], bb[j], acc[i][j]);
        }
        if (kt + 1 < KT) {
            const int nb = buf ^ 1;
            ST_TILE(As[nb], kq, r0, pa0); ST_TILE(As[nb], kq, r1, pa1);
            ST_TILE(Bs[nb], kq, r0, pb0); ST_TILE(Bs[nb], kq, r1, pb1);
        }
        __syncthreads();
        buf ^= 1;
    }

    // epilogue: bias + PReLU + transpose-scatter
    const float pa_ = __ldg(pap);
    float bias[8];
    #pragma unroll
    for (int j = 0; j < 8; ++j) bias[j] = __ldg(b_out + n0 + tx * 8 + j);
    #pragma unroll
    for (int i = 0; i < 8; ++i) {
        const int m = m0 + ty * 8 + i;
        const int bb2 = m >> 10, tt = m & 1023;
        float* orow = out1 + ((size_t)tt * NB + bb2) * ND + n0 + tx * 8;
        float h[8];
        #pragma unroll
        for (int j = 0; j < 8; ++j) {
            float v = acc[i][j] + bias[j];
            h[j] = (v >= 0.0f) ? v : pa_ * v;
        }
        *(float4*)(orow)     = make_float4(h[0], h[1], h[2], h[3]);
        *(float4*)(orow + 4) = make_float4(h[4], h[5], h[6], h[7]);
    }
}

// ---------------------------------------------------------------------------
extern "C" void kernel_launch(void* const* d_in, const int* in_sizes, int n_in,
                              void* d_out, int out_size)
{
    const float* inp = (const float*)d_in[0];   // [B,T,768]
    const float* ctx = (const float*)d_in[1];   // [B,S,768]
    const float* W   = (const float*)d_in[2];   // [768,1536]
    const float* bo  = (const float*)d_in[3];   // [768]
    const float* ws  = (const float*)d_in[4];   // [1]
    const float* bs  = (const float*)d_in[5];   // [1]
    const float* pa  = (const float*)d_in[6];   // [1]
    float* out1 = (float*)d_out;                          // attn_h^T [T,B,768]
    float* out2 = out1 + (size_t)NTT * NB * ND;           // av_g^T   [T,B,S]

    gemm1_nt   <<<dim3(8, 8, NB), 256>>>(inp, ctx);
    softmax_k  <<<NB * NTT, 256>>>();
    gate_k     <<<NB * NSS / 256, 256>>>();
    avg_k      <<<NB * NTT, 256>>>(out2);
    gemm2_nn   <<<dim3(6, 8, NB), 256>>>(out2, ctx);
    gemm3_fused<<<dim3(6, 128), 256>>>(inp, W, bo, ws, bs, pa, out1);
}

// round 3
// speedup vs baseline: 2.5702x; 2.5702x over previous
#include <cuda_runtime.h>
#include <cuda_bf16.h>
#include <stdint.h>
#include <math.h>

#define NB 16
#define NTT 1024
#define NSS 1024
#define ND 768
#define NK3 1536

// ---------------------------------------------------------------------------
// scratch (static device globals — no allocations allowed)
// ---------------------------------------------------------------------------
__device__ float g_scores[(size_t)NB * NTT * NSS];         // logits -> av (in place)
__device__ float g_gate[NB * NSS];
__device__ __nv_bfloat16 g_inp_hi[(size_t)NB * NTT * ND];
__device__ __nv_bfloat16 g_inp_lo[(size_t)NB * NTT * ND];
__device__ __nv_bfloat16 g_ctx_hi[(size_t)NB * NSS * ND];
__device__ __nv_bfloat16 g_ctx_lo[(size_t)NB * NSS * ND];
__device__ __nv_bfloat16 g_ctxT_hi[(size_t)NB * ND * NSS];
__device__ __nv_bfloat16 g_ctxT_lo[(size_t)NB * ND * NSS];
__device__ __nv_bfloat16 g_avg_hi[(size_t)NB * NTT * NSS];
__device__ __nv_bfloat16 g_avg_lo[(size_t)NB * NTT * NSS];
__device__ __nv_bfloat16 g_cc_hi[(size_t)NB * NTT * ND];
__device__ __nv_bfloat16 g_cc_lo[(size_t)NB * NTT * ND];
__device__ __nv_bfloat16 g_w_hi[ND * NK3];
__device__ __nv_bfloat16 g_w_lo[ND * NK3];

// ---------------------------------------------------------------------------
// sm_80-compatible PTX helpers (NO tcgen05 — harness targets compute_103)
// ---------------------------------------------------------------------------
__device__ __forceinline__ uint32_t smem_to_u32(const void* p) {
    uint32_t a;
    asm("{ .reg .u64 t; cvta.to.shared.u64 t, %1; cvt.u32.u64 %0, t; }" : "=r"(a) : "l"(p));
    return a;
}

__device__ __forceinline__ void cpa16(uint32_t dst, const void* src) {
    asm volatile("cp.async.cg.shared.global [%0], [%1], 16;" :: "r"(dst), "l"(src));
}
#define CP_COMMIT() asm volatile("cp.async.commit_group;" ::: "memory")
#define CP_WAIT(n)  asm volatile("cp.async.wait_group %0;" :: "n"(n) : "memory")

__device__ __forceinline__ void ldsm4(uint32_t (&r)[4], uint32_t addr) {
    asm volatile("ldmatrix.sync.aligned.m8n8.x4.shared.b16 {%0,%1,%2,%3}, [%4];"
                 : "=r"(r[0]), "=r"(r[1]), "=r"(r[2]), "=r"(r[3]) : "r"(addr));
}

__device__ __forceinline__ void hmma(float (&d)[4], const uint32_t (&a)[4],
                                     uint32_t b0, uint32_t b1) {
    asm volatile(
        "mma.sync.aligned.m16n8k16.row.col.f32.bf16.bf16.f32 "
        "{%0,%1,%2,%3}, {%4,%5,%6,%7}, {%8,%9}, {%0,%1,%2,%3};"
        : "+f"(d[0]), "+f"(d[1]), "+f"(d[2]), "+f"(d[3])
        : "r"(a[0]), "r"(a[1]), "r"(a[2]), "r"(a[3]), "r"(b0), "r"(b1));
}

// byte offset of bf16 (r, c) inside a 128x64-bf16 SW128-swizzled tile
__device__ __forceinline__ uint32_t swz(int r, int c) {
    int off = (r << 7) + (c << 1);
    return (uint32_t)(off ^ ((off >> 3) & 0x70));
}

static constexpr int TILE_B   = 16384;      // one 128x64 bf16 tile
static constexpr int STAGE_B  = 4 * TILE_B; // Ah, Al, Bh, Bl
static constexpr int SMEM_BYTES = 2 * STAGE_B;  // 131072

// async-load one stage: 4 tiles of 128 rows x 64 bf16, SW128 swizzled
__device__ __forceinline__ void load_stage_async(
    const __nv_bfloat16* __restrict__ ah, const __nv_bfloat16* __restrict__ al,
    const __nv_bfloat16* __restrict__ bh, const __nv_bfloat16* __restrict__ bl,
    int lda, int ldb, int m0, int n0, int ka, int kb, uint32_t sbase)
{
    const int tid = threadIdx.x;
    #pragma unroll
    for (int j = 0; j < 4; ++j) {
        const int id = tid + 256 * j;         // 0..1023
        const int r  = id >> 3;               // 0..127
        const int c  = (id & 7) << 3;         // 0,8,...,56
        const uint32_t off = swz(r, c);
        cpa16(sbase + off,              ah + (size_t)(m0 + r) * lda + ka + c);
        cpa16(sbase + TILE_B + off,     al + (size_t)(m0 + r) * lda + ka + c);
        cpa16(sbase + 2 * TILE_B + off, bh + (size_t)(n0 + r) * ldb + kb + c);
        cpa16(sbase + 3 * TILE_B + off, bl + (size_t)(n0 + r) * ldb + kb + c);
    }
}

// ---------------------------------------------------------------------------
// 128x128-tile split-bf16 HMMA GEMM (3-term: AhBh + AhBl + AlBh)
//   MODE 0: scores = inp @ ctx^T           (K=768)  -> g_scores fp32
//   MODE 1: cc = (avg @ ctxT^T) * ws + bs  (K=1024) -> cc_hi/cc_lo
//   MODE 2: h = [cc;inp] @ W^T + b, PReLU  (K=1536) -> out1 [T,B,D]
// ---------------------------------------------------------------------------
template <int MODE>
__global__ __launch_bounds__(256)
void hmma_gemm(const float* __restrict__ wsp, const float* __restrict__ bsp,
               const float* __restrict__ biasp, const float* __restrict__ pap,
               float* __restrict__ out1)
{
    extern __shared__ char smem[];
    const uint32_t sb = smem_to_u32(smem);
    const int tid = threadIdx.x;
    const int lane = tid & 31, wid = tid >> 5;
    const int rm = (wid & 3) * 32;     // warp row base in tile
    const int cn = (wid >> 2) * 64;    // warp col base in tile

    const int m0 = blockIdx.y * 128;
    const int n0 = blockIdx.x * 128;
    const int bz = blockIdx.z;

    int K, lda, ldb;
    const __nv_bfloat16 *Ah, *Al, *Bh, *Bl;
    if (MODE == 0) {
        K = ND; lda = ND; ldb = ND;
        Ah = g_inp_hi + (size_t)bz * NTT * ND;  Al = g_inp_lo + (size_t)bz * NTT * ND;
        Bh = g_ctx_hi + (size_t)bz * NSS * ND;  Bl = g_ctx_lo + (size_t)bz * NSS * ND;
    } else if (MODE == 1) {
        K = NSS; lda = NSS; ldb = NSS;
        Ah = g_avg_hi + (size_t)bz * NTT * NSS;  Al = g_avg_lo + (size_t)bz * NTT * NSS;
        Bh = g_ctxT_hi + (size_t)bz * ND * NSS;  Bl = g_ctxT_lo + (size_t)bz * ND * NSS;
    } else {
        K = NK3; lda = ND; ldb = NK3;
        Ah = g_cc_hi;  Al = g_cc_lo;
        Bh = g_w_hi;   Bl = g_w_lo;
    }
    const int NC = K / 64;

    float acc[2][8][4];
    #pragma unroll
    for (int i = 0; i < 2; ++i)
        #pragma unroll
        for (int j = 0; j < 8; ++j)
            #pragma unroll
            for (int v = 0; v < 4; ++v) acc[i][j][v] = 0.f;

    // precomputed ldmatrix lane address components
    const int q = lane >> 3, l7 = lane & 7;
    const int ar = rm + ((q & 1) << 3) + l7;      // A: matrix q -> m offset
    const int acq = (q >> 1) << 3;                // A: matrix q -> k offset
    const int brq = ((q >> 1) << 3) + l7;         // B: matrix q -> n offset
    const int bcq = (q & 1) << 3;                 // B: matrix q -> k offset

    // prologue: stage 0
    {
        const __nv_bfloat16 *ah = Ah, *al = Al;
        int ka = 0;
        load_stage_async(ah, al, Bh, Bl, lda, ldb, m0, n0, ka, 0, sb);
        CP_COMMIT();
    }

    for (int kc = 0; kc < NC; ++kc) {
        if (kc + 1 < NC) {
            const __nv_bfloat16 *ah = Ah, *al = Al;
            int ka = (kc + 1) * 64;
            const int kb = ka;
            if (MODE == 2 && ka >= ND) { ah = g_inp_hi; al = g_inp_lo; ka -= ND; }
            load_stage_async(ah, al, Bh, Bl, lda, ldb, m0, n0, ka, kb,
                             sb + (uint32_t)((kc + 1) & 1) * STAGE_B);
            CP_COMMIT();
            CP_WAIT(1);
        } else {
            CP_WAIT(0);
        }
        __syncthreads();

        const uint32_t sbase = sb + (uint32_t)(kc & 1) * STAGE_B;
        #pragma unroll
        for (int k16 = 0; k16 < 4; ++k16) {
            const int kk = k16 * 16;
            uint32_t Ah0[4], Ah1[4], Al0[4], Al1[4];
            ldsm4(Ah0, sbase + swz(ar, kk + acq));
            ldsm4(Ah1, sbase + swz(ar + 16, kk + acq));
            ldsm4(Al0, sbase + TILE_B + swz(ar, kk + acq));
            ldsm4(Al1, sbase + TILE_B + swz(ar + 16, kk + acq));
            #pragma unroll
            for (int np = 0; np < 4; ++np) {
                uint32_t Bh4[4], Bl4[4];
                const uint32_t boff = swz(cn + np * 16 + brq, kk + bcq);
                ldsm4(Bh4, sbase + 2 * TILE_B + boff);
                ldsm4(Bl4, sbase + 3 * TILE_B + boff);
                hmma(acc[0][2 * np],     Ah0, Bh4[0], Bh4[1]);
                hmma(acc[0][2 * np + 1], Ah0, Bh4[2], Bh4[3]);
                hmma(acc[1][2 * np],     Ah1, Bh4[0], Bh4[1]);
                hmma(acc[1][2 * np + 1], Ah1, Bh4[2], Bh4[3]);
                hmma(acc[0][2 * np],     Ah0, Bl4[0], Bl4[1]);
                hmma(acc[0][2 * np + 1], Ah0, Bl4[2], Bl4[3]);
                hmma(acc[1][2 * np],     Ah1, Bl4[0], Bl4[1]);
                hmma(acc[1][2 * np + 1], Ah1, Bl4[2], Bl4[3]);
                hmma(acc[0][2 * np],     Al0, Bh4[0], Bh4[1]);
                hmma(acc[0][2 * np + 1], Al0, Bh4[2], Bh4[3]);
                hmma(acc[1][2 * np],     Al1, Bh4[0], Bh4[1]);
                hmma(acc[1][2 * np + 1], Al1, Bh4[2], Bh4[3]);
            }
        }
        __syncthreads();
    }

    // -----------------------------------------------------------------------
    // epilogue: acc[mt][nt][v] -> (row, col):
    //   rows: m0 + rm + mt*16 + (lane>>2) + {0,8}
    //   cols: n0 + cn + nt*8 + 2*(lane&3) + {0,1}
    // -----------------------------------------------------------------------
    const int rbase = m0 + rm + (lane >> 2);
    const int cbase = n0 + cn + ((lane & 3) << 1);

    if (MODE == 0) {
        float* dst = g_scores + ((size_t)bz << 20);
        #pragma unroll
        for (int mt = 0; mt < 2; ++mt)
            #pragma unroll
            for (int h = 0; h < 2; ++h) {
                const int row = rbase + mt * 16 + h * 8;
                #pragma unroll
                for (int nt = 0; nt < 8; ++nt) {
                    *(float2*)(dst + (size_t)row * NSS + cbase + nt * 8) =
                        make_float2(acc[mt][nt][2 * h], acc[mt][nt][2 * h + 1]);
                }
            }
    } else if (MODE == 1) {
        const float ws = __ldg(wsp), bs = __ldg(bsp);
        #pragma unroll
        for (int mt = 0; mt < 2; ++mt)
            #pragma unroll
            for (int h = 0; h < 2; ++h) {
                const int row = rbase + mt * 16 + h * 8;
                const size_t base = ((size_t)bz * NTT + row) * ND;
                #pragma unroll
                for (int nt = 0; nt < 8; ++nt) {
                    const float v0 = fmaf(acc[mt][nt][2 * h], ws, bs);
                    const float v1 = fmaf(acc[mt][nt][2 * h + 1], ws, bs);
                    __nv_bfloat16 h0 = __float2bfloat16(v0);
                    __nv_bfloat16 h1 = __float2bfloat16(v1);
                    __nv_bfloat16 l0 = __float2bfloat16(v0 - __bfloat162float(h0));
                    __nv_bfloat16 l1 = __float2bfloat16(v1 - __bfloat162float(h1));
                    const size_t o = base + cbase + nt * 8;
                    *(__nv_bfloat162*)(g_cc_hi + o) = __halves2bfloat162(h0, h1);
                    *(__nv_bfloat162*)(g_cc_lo + o) = __halves2bfloat162(l0, l1);
                }
            }
    } else {
        const float pa = __ldg(pap);
        #pragma unroll
        for (int mt = 0; mt < 2; ++mt)
            #pragma unroll
            for (int h = 0; h < 2; ++h) {
                const int row = rbase + mt * 16 + h * 8;    // global m in [0,16384)
                const int bb = row >> 10, tt = row & 1023;
                float* dst = out1 + ((size_t)tt * NB + bb) * ND;
                #pragma unroll
                for (int nt = 0; nt < 8; ++nt) {
                    const int col = cbase + nt * 8;
                    float v0 = acc[mt][nt][2 * h]     + __ldg(biasp + col);
                    float v1 = acc[mt][nt][2 * h + 1] + __ldg(biasp + col + 1);
                    v0 = (v0 >= 0.f) ? v0 : pa * v0;
                    v1 = (v1 >= 0.f) ? v1 : pa * v1;
                    *(float2*)(dst + col) = make_float2(v0, v1);
                }
            }
    }
}

// ---------------------------------------------------------------------------
// fp32 -> bf16 hi/lo split (plain layout)
// ---------------------------------------------------------------------------
__global__ __launch_bounds__(256)
void split_k(const float* __restrict__ src, __nv_bfloat16* __restrict__ hi,
             __nv_bfloat16* __restrict__ lo)
{
    const size_t i = (size_t)blockIdx.x * 256 + threadIdx.x;
    float4 v = ((const float4*)src)[i];
    __nv_bfloat16 h0 = __float2bfloat16(v.x), h1 = __float2bfloat16(v.y);
    __nv_bfloat16 h2 = __float2bfloat16(v.z), h3 = __float2bfloat16(v.w);
    __nv_bfloat16 l0 = __float2bfloat16(v.x - __bfloat162float(h0));
    __nv_bfloat16 l1 = __float2bfloat16(v.y - __bfloat162float(h1));
    __nv_bfloat16 l2 = __float2bfloat16(v.z - __bfloat162float(h2));
    __nv_bfloat16 l3 = __float2bfloat16(v.w - __bfloat162float(h3));
    ((__nv_bfloat162*)hi)[2 * i]     = __halves2bfloat162(h0, h1);
    ((__nv_bfloat162*)hi)[2 * i + 1] = __halves2bfloat162(h2, h3);
    ((__nv_bfloat162*)lo)[2 * i]     = __halves2bfloat162(l0, l1);
    ((__nv_bfloat162*)lo)[2 * i + 1] = __halves2bfloat162(l2, l3);
}

// ---------------------------------------------------------------------------
// ctx [b,s,d] -> ctxT [b,d,s] transpose + hi/lo split
// ---------------------------------------------------------------------------
__global__ __launch_bounds__(256)
void split_tr(const float* __restrict__ ctx, __nv_bfloat16* __restrict__ th,
              __nv_bfloat16* __restrict__ tl)
{
    __shared__ float ts[32][33];
    const int b = blockIdx.z;
    const int d0 = blockIdx.x * 32;
    const int s0 = blockIdx.y * 32;
    const int tx = threadIdx.x, ty = threadIdx.y;   // 32 x 8
    #pragma unroll
    for (int r = ty; r < 32; r += 8)
        ts[r][tx] = ctx[(size_t)b * NSS * ND + (size_t)(s0 + r) * ND + d0 + tx];
    __syncthreads();
    #pragma unroll
    for (int r = ty; r < 32; r += 8) {
        float v = ts[tx][r];
        __nv_bfloat16 h = __float2bfloat16(v);
        __nv_bfloat16 l = __float2bfloat16(v - __bfloat162float(h));
        const size_t o = (size_t)b * ND * NSS + (size_t)(d0 + r) * NSS + s0 + tx;
        th[o] = h;
        tl[o] = l;
    }
}

// ---------------------------------------------------------------------------
// row softmax over S (in place on g_scores)
// ---------------------------------------------------------------------------
__global__ __launch_bounds__(256)
void softmax_k()
{
    float* row = g_scores + (size_t)blockIdx.x * NSS;
    const int tid = threadIdx.x;
    const unsigned FULL = 0xffffffffu;
    float4 x = *(float4*)(row + tid * 4);
    float m = fmaxf(fmaxf(x.x, x.y), fmaxf(x.z, x.w));
    __shared__ float sred[8];
    __shared__ float sred2[8];
    #pragma unroll
    for (int o = 16; o; o >>= 1) m = fmaxf(m, __shfl_xor_sync(FULL, m, o));
    if ((tid & 31) == 0) sred[tid >> 5] = m;
    __syncthreads();
    m = fmaxf(fmaxf(fmaxf(sred[0], sred[1]), fmaxf(sred[2], sred[3])),
              fmaxf(fmaxf(sred[4], sred[5]), fmaxf(sred[6], sred[7])));
    float e0 = expf(x.x - m), e1 = expf(x.y - m), e2 = expf(x.z - m), e3 = expf(x.w - m);
    float s = (e0 + e1) + (e2 + e3);
    #pragma unroll
    for (int o = 16; o; o >>= 1) s += __shfl_xor_sync(FULL, s, o);
    if ((tid & 31) == 0) sred2[tid >> 5] = s;
    __syncthreads();
    s = ((sred2[0] + sred2[1]) + (sred2[2] + sred2[3])) +
        ((sred2[4] + sred2[5]) + (sred2[6] + sred2[7]));
    const float inv = 1.0f / s;
    *(float4*)(row + tid * 4) = make_float4(e0 * inv, e1 * inv, e2 * inv, e3 * inv);
}

// ---------------------------------------------------------------------------
// gate[b,s] = sigmoid( sum_t av[b,t,s] )
// ---------------------------------------------------------------------------
__global__ __launch_bounds__(256)
void gate_k()
{
    const int gid = blockIdx.x * 256 + threadIdx.x;
    const int b = gid >> 10, s = gid & 1023;
    const float* p = g_scores + (size_t)b * NTT * NSS + s;
    float a[8] = {};
    for (int t = 0; t < NTT; t += 8) {
        #pragma unroll
        for (int u = 0; u < 8; ++u) a[u] += p[(size_t)(t + u) * NSS];
    }
    const float sum = ((a[0] + a[1]) + (a[2] + a[3])) + ((a[4] + a[5]) + (a[6] + a[7]));
    g_gate[gid] = 1.0f / (1.0f + expf(-sum));
}

// ---------------------------------------------------------------------------
// av_g: fp32 -> out2 [T,B,S] (output) AND bf16 hi/lo [B,T,S] (GEMM2 A operand)
// ---------------------------------------------------------------------------
__global__ __launch_bounds__(256)
void avg_k(float* __restrict__ out2)
{
    const int bt = blockIdx.x;
    const int b = bt >> 10, t = bt & 1023;
    const int s = threadIdx.x * 4;
    float4 v = *(const float4*)(g_scores + (size_t)bt * NSS + s);
    float4 g = *(const float4*)(g_gate + b * NSS + s);
    const float pool = 1.0f / 1024.0f;
    v.x *= g.x * pool; v.y *= g.y * pool; v.z *= g.z * pool; v.w *= g.w * pool;
    *(float4*)(out2 + ((size_t)t * NB + b) * NSS + s) = v;

    __nv_bfloat16 h0 = __float2bfloat16(v.x), h1 = __float2bfloat16(v.y);
    __nv_bfloat16 h2 = __float2bfloat16(v.z), h3 = __float2bfloat16(v.w);
    __nv_bfloat16 l0 = __float2bfloat16(v.x - __bfloat162float(h0));
    __nv_bfloat16 l1 = __float2bfloat16(v.y - __bfloat162float(h1));
    __nv_bfloat16 l2 = __float2bfloat16(v.z - __bfloat162float(h2));
    __nv_bfloat16 l3 = __float2bfloat16(v.w - __bfloat162float(h3));
    __nv_bfloat162* ph = (__nv_bfloat162*)(g_avg_hi + (size_t)bt * NSS + s);
    __nv_bfloat162* pl = (__nv_bfloat162*)(g_avg_lo + (size_t)bt * NSS + s);
    ph[0] = __halves2bfloat162(h0, h1);
    ph[1] = __halves2bfloat162(h2, h3);
    pl[0] = __halves2bfloat162(l0, l1);
    pl[1] = __halves2bfloat162(l2, l3);
}

// ---------------------------------------------------------------------------
extern "C" void kernel_launch(void* const* d_in, const int* in_sizes, int n_in,
                              void* d_out, int out_size)
{
    const float* inp = (const float*)d_in[0];   // [B,T,768]
    const float* ctx = (const float*)d_in[1];   // [B,S,768]
    const float* W   = (const float*)d_in[2];   // [768,1536]
    const float* bo  = (const float*)d_in[3];   // [768]
    const float* ws  = (const float*)d_in[4];   // [1]
    const float* bs  = (const float*)d_in[5];   // [1]
    const float* pa  = (const float*)d_in[6];   // [1]
    float* out1 = (float*)d_out;                          // attn_h^T [T,B,768]
    float* out2 = out1 + (size_t)NTT * NB * ND;           // av_g^T   [T,B,S]

    cudaFuncSetAttribute(hmma_gemm<0>, cudaFuncAttributeMaxDynamicSharedMemorySize, SMEM_BYTES);
    cudaFuncSetAttribute(hmma_gemm<1>, cudaFuncAttributeMaxDynamicSharedMemorySize, SMEM_BYTES);
    cudaFuncSetAttribute(hmma_gemm<2>, cudaFuncAttributeMaxDynamicSharedMemorySize, SMEM_BYTES);

    __nv_bfloat16 *inp_hi, *inp_lo, *ctx_hi, *ctx_lo, *ctxT_hi, *ctxT_lo, *w_hi, *w_lo;
    cudaGetSymbolAddress((void**)&inp_hi, g_inp_hi);
    cudaGetSymbolAddress((void**)&inp_lo, g_inp_lo);
    cudaGetSymbolAddress((void**)&ctx_hi, g_ctx_hi);
    cudaGetSymbolAddress((void**)&ctx_lo, g_ctx_lo);
    cudaGetSymbolAddress((void**)&ctxT_hi, g_ctxT_hi);
    cudaGetSymbolAddress((void**)&ctxT_lo, g_ctxT_lo);
    cudaGetSymbolAddress((void**)&w_hi, g_w_hi);
    cudaGetSymbolAddress((void**)&w_lo, g_w_lo);

    split_k<<<NB * NTT * ND / 4 / 256, 256>>>(inp, inp_hi, inp_lo);
    split_k<<<NB * NSS * ND / 4 / 256, 256>>>(ctx, ctx_hi, ctx_lo);
    split_k<<<ND * NK3 / 4 / 256, 256>>>(W, w_hi, w_lo);
    split_tr<<<dim3(ND / 32, NSS / 32, NB), dim3(32, 8)>>>(ctx, ctxT_hi, ctxT_lo);

    hmma_gemm<0><<<dim3(8, 8, NB), 256, SMEM_BYTES>>>(ws, bs, bo, pa, out1);
    softmax_k<<<NB * NTT, 256>>>();
    gate_k<<<NB * NSS / 256, 256>>>();
    avg_k<<<NB * NTT, 256>>>(out2);
    hmma_gemm<1><<<dim3(6, 8, NB), 256, SMEM_BYTES>>>(ws, bs, bo, pa, out1);
    hmma_gemm<2><<<dim3(6, 128, 1), 256, SMEM_BYTES>>>(ws, bs, bo, pa, out1);
}